// round 1
// baseline (speedup 1.0000x reference)
#include <cuda_runtime.h>
#include <math.h>
#include <stdint.h>

#define N_NODES 20000
#define N_EDGES 320000
#define H 128
#define CUTOFF_R 5.0f

// ---------------- scratch (device globals: allocation-free) ----------------
__device__ __align__(16) float g_scalar_out[N_NODES * H];       // layernorm(node_scalar)
__device__ __align__(16) float g_ns[N_NODES * H];               // scalar_out @ W_node + b
__device__ __align__(16) float g_ef[N_EDGES * H];               // silu(edge_feats @ W_edge + b)
__device__ __align__(16) float g_msg[N_EDGES * H];              // message
__device__ __align__(16) float g_s[N_EDGES * 2 * H];            // silu(msg @ W_p1 + b): s1|s2
__device__ __align__(16) float g_gf[N_EDGES * H];               // silu(edge_feats @ W_f + b)
__device__ __align__(16) float g_nv[N_NODES * 3 * H];           // node_vector @ W_cross
__device__ __align__(16) float g_ns1[N_NODES * H];              // node_scalar + scalar_agg
__device__ __align__(16) float g_nvec1[N_NODES * 3 * H];        // node_vector + vector_agg
__device__ __align__(16) float g_wv[N_NODES * 3 * 2 * H];       // nvec1 @ W_vec  (v1|v2)
__device__ __align__(16) float g_p[N_NODES * 3 * H];            // ns1 @ W_p2 + b (p1|p2|p3)

__device__ int g_deg[N_NODES];
__device__ int g_off[N_NODES + 1];
__device__ int g_cur[N_NODES];
__device__ int g_eids[N_EDGES];

// ---------------- helpers ----------------
__device__ __forceinline__ float silu_f(float x) {
    return x / (1.0f + __expf(-x));
}

// ---------------- layernorm over H=128, one block per node ----------------
__global__ void ln_kernel(const float* __restrict__ x,
                          const float* __restrict__ gamma,
                          const float* __restrict__ beta,
                          float* __restrict__ y) {
    int n = blockIdx.x;
    int h = threadIdx.x;
    float v = x[(size_t)n * H + h];
    float s = v, s2 = v * v;
    #pragma unroll
    for (int o = 16; o > 0; o >>= 1) {
        s  += __shfl_xor_sync(0xffffffffu, s, o);
        s2 += __shfl_xor_sync(0xffffffffu, s2, o);
    }
    __shared__ float rs[4], rs2[4];
    int warp = h >> 5, lane = h & 31;
    if (lane == 0) { rs[warp] = s; rs2[warp] = s2; }
    __syncthreads();
    float ts  = rs[0] + rs[1] + rs[2] + rs[3];
    float ts2 = rs2[0] + rs2[1] + rs2[2] + rs2[3];
    float mu  = ts * (1.0f / H);
    float var = ts2 * (1.0f / H) - mu * mu;
    float inv = rsqrtf(var + 1e-5f);
    y[(size_t)n * H + h] = (v - mu) * inv * gamma[h] + beta[h];
}

// ---------------- generic SGEMM: C[M,NCOL] = act(A[M,128] @ W[128,NCOL] + bias) --
// BM=BN=128, BK=16, 256 threads, 8x8 per-thread register tile.
__global__ void gemm128(const float* __restrict__ A,
                        const float* __restrict__ W,
                        const float* __restrict__ bias,
                        float* __restrict__ C,
                        int M, int NCOL, int act) {
    __shared__ float As[16][128];
    __shared__ float Ws[16][128];
    const int bm = blockIdx.x * 128;
    const int bn = blockIdx.y * 128;
    const int tid = threadIdx.x;
    const int tx = tid & 15, ty = tid >> 4;

    float acc[8][8];
    #pragma unroll
    for (int i = 0; i < 8; i++)
        #pragma unroll
        for (int j = 0; j < 8; j++) acc[i][j] = 0.0f;

    const int lm = tid >> 1;
    const int lk = (tid & 1) << 3;
    const int wk = tid >> 4;
    const int wn = (tid & 15) << 3;
    const int arow = bm + lm;

    for (int k0 = 0; k0 < 128; k0 += 16) {
        float4 a0, a1;
        if (arow < M) {
            const float4* p = reinterpret_cast<const float4*>(A + (size_t)arow * 128 + k0 + lk);
            a0 = p[0]; a1 = p[1];
        } else {
            a0 = make_float4(0.f, 0.f, 0.f, 0.f); a1 = a0;
        }
        As[lk + 0][lm] = a0.x; As[lk + 1][lm] = a0.y;
        As[lk + 2][lm] = a0.z; As[lk + 3][lm] = a0.w;
        As[lk + 4][lm] = a1.x; As[lk + 5][lm] = a1.y;
        As[lk + 6][lm] = a1.z; As[lk + 7][lm] = a1.w;

        const float4* q = reinterpret_cast<const float4*>(W + (size_t)(k0 + wk) * NCOL + bn + wn);
        float4 w0 = q[0], w1 = q[1];
        *reinterpret_cast<float4*>(&Ws[wk][wn])     = w0;
        *reinterpret_cast<float4*>(&Ws[wk][wn + 4]) = w1;
        __syncthreads();

        #pragma unroll
        for (int k = 0; k < 16; k++) {
            float ar[8], wr[8];
            *reinterpret_cast<float4*>(ar)     = *reinterpret_cast<const float4*>(&As[k][ty * 8]);
            *reinterpret_cast<float4*>(ar + 4) = *reinterpret_cast<const float4*>(&As[k][ty * 8 + 4]);
            *reinterpret_cast<float4*>(wr)     = *reinterpret_cast<const float4*>(&Ws[k][tx * 8]);
            *reinterpret_cast<float4*>(wr + 4) = *reinterpret_cast<const float4*>(&Ws[k][tx * 8 + 4]);
            #pragma unroll
            for (int i = 0; i < 8; i++)
                #pragma unroll
                for (int j = 0; j < 8; j++)
                    acc[i][j] = fmaf(ar[i], wr[j], acc[i][j]);
        }
        __syncthreads();
    }

    float bv[8];
    #pragma unroll
    for (int j = 0; j < 8; j++) bv[j] = bias ? bias[bn + tx * 8 + j] : 0.0f;

    #pragma unroll
    for (int i = 0; i < 8; i++) {
        int row = bm + ty * 8 + i;
        if (row >= M) continue;
        float out[8];
        #pragma unroll
        for (int j = 0; j < 8; j++) {
            float v = acc[i][j] + bv[j];
            if (act) v = silu_f(v);
            out[j] = v;
        }
        float4* dst = reinterpret_cast<float4*>(C + (size_t)row * NCOL + bn + tx * 8);
        dst[0] = *reinterpret_cast<float4*>(out);
        dst[1] = *reinterpret_cast<float4*>(out + 4);
    }
}

// ---------------- CSR build ----------------
__global__ void csr_zero() {
    int n = blockIdx.x * blockDim.x + threadIdx.x;
    if (n < N_NODES) g_deg[n] = 0;
}
__global__ void csr_hist(const int* __restrict__ ei) {
    int e = blockIdx.x * blockDim.x + threadIdx.x;
    if (e < N_EDGES) atomicAdd(&g_deg[ei[e]], 1);
}
__global__ void csr_scan() {
    __shared__ int sh[1024];
    __shared__ int carry;
    int tid = threadIdx.x;
    if (tid == 0) carry = 0;
    for (int base = 0; base < N_NODES; base += 1024) {
        __syncthreads();
        int c = carry;
        int idx = base + tid;
        int v = (idx < N_NODES) ? g_deg[idx] : 0;
        sh[tid] = v;
        __syncthreads();
        #pragma unroll
        for (int o = 1; o < 1024; o <<= 1) {
            int t = (tid >= o) ? sh[tid - o] : 0;
            __syncthreads();
            sh[tid] += t;
            __syncthreads();
        }
        if (idx < N_NODES) {
            int excl = c + sh[tid] - v;
            g_off[idx] = excl;
            g_cur[idx] = excl;
        }
        int tot = sh[1023];
        __syncthreads();
        if (tid == 0) carry = c + tot;
    }
    __syncthreads();
    if (tid == 0) g_off[N_NODES] = carry;
}
__global__ void csr_scatter(const int* __restrict__ ei) {
    int e = blockIdx.x * blockDim.x + threadIdx.x;
    if (e < N_EDGES) {
        int i = ei[e];
        int pos = atomicAdd(&g_cur[i], 1);
        g_eids[pos] = e;
    }
}

// ---------------- edge message: attn + msg ----------------
__global__ void edge_msg(const int* __restrict__ ei,
                         const float* __restrict__ dist,
                         const float* __restrict__ alpha) {
    int e = blockIdx.x;
    int h = threadIdx.x;
    int i = ei[e], j = ei[N_EDGES + e];
    float nsi = g_ns[(size_t)i * H + h];
    float nsj = g_ns[(size_t)j * H + h];
    float ef  = g_ef[(size_t)e * H + h];
    float x = nsi + nsj + ef;
    float t = silu_f(x) * alpha[h];
    // sum over 16-lane head groups (HD=16)
    t += __shfl_xor_sync(0xffffffffu, t, 1);
    t += __shfl_xor_sync(0xffffffffu, t, 2);
    t += __shfl_xor_sync(0xffffffffu, t, 4);
    t += __shfl_xor_sync(0xffffffffu, t, 8);
    float d = dist[e];
    float cut = 0.5f * (__cosf(3.14159265358979323846f * d / CUTOFF_R) + 1.0f);
    cut = (d < CUTOFF_R) ? cut : 0.0f;
    g_msg[(size_t)e * H + h] = nsj * ef * (t * cut);
}

// ---------------- aggregation (gather over CSR) + residual ----------------
__global__ void aggregate(const int* __restrict__ ei,
                          const float* __restrict__ ev,
                          const float* __restrict__ nscal,
                          const float* __restrict__ nvec) {
    int n = blockIdx.x;
    int h = threadIdx.x;
    float as = 0.0f, av0 = 0.0f, av1 = 0.0f, av2 = 0.0f;
    int beg = g_off[n], end = g_off[n + 1];
    for (int idx = beg; idx < end; idx++) {
        int e = g_eids[idx];
        int j = ei[N_EDGES + e];
        float m  = g_msg[(size_t)e * H + h];
        float sa = g_s[(size_t)e * 256 + h];
        float sb = g_s[(size_t)e * 256 + 128 + h];
        float e0 = ev[e * 3 + 0], e1 = ev[e * 3 + 1], e2 = ev[e * 3 + 2];
        as  += m;
        av0 += nvec[((size_t)j * 3 + 0) * H + h] * sa + sb * e0;
        av1 += nvec[((size_t)j * 3 + 1) * H + h] * sa + sb * e1;
        av2 += nvec[((size_t)j * 3 + 2) * H + h] * sa + sb * e2;
    }
    g_ns1[(size_t)n * H + h] = nscal[(size_t)n * H + h] + as;
    g_nvec1[((size_t)n * 3 + 0) * H + h] = nvec[((size_t)n * 3 + 0) * H + h] + av0;
    g_nvec1[((size_t)n * 3 + 1) * H + h] = nvec[((size_t)n * 3 + 1) * H + h] + av1;
    g_nvec1[((size_t)n * 3 + 2) * H + h] = nvec[((size_t)n * 3 + 2) * H + h] + av2;
}

// ---------------- edge update: sum_phi via Lagrange identity ----------------
__global__ void edge_final(const int* __restrict__ ei,
                           const float* __restrict__ ev,
                           const float* __restrict__ efeat,
                           float* __restrict__ out_edge) {
    int e = blockIdx.x;
    int h = threadIdx.x;
    int i = ei[e], j = ei[N_EDGES + e];
    float v0 = ev[e * 3 + 0], v1 = ev[e * 3 + 1], v2 = ev[e * 3 + 2];
    float a0 = g_nv[((size_t)i * 3 + 0) * H + h];
    float a1 = g_nv[((size_t)i * 3 + 1) * H + h];
    float a2 = g_nv[((size_t)i * 3 + 2) * H + h];
    float b0 = g_nv[((size_t)j * 3 + 0) * H + h];
    float b1 = g_nv[((size_t)j * 3 + 1) * H + h];
    float b2 = g_nv[((size_t)j * 3 + 2) * H + h];
    float ab = a0 * b0 + a1 * b1 + a2 * b2;
    float av = a0 * v0 + a1 * v1 + a2 * v2;
    float bv = b0 * v0 + b1 * v1 + b2 * v2;
    float vv = v0 * v0 + v1 * v1 + v2 * v2;
    float sum_phi = ab * vv - av * bv;  // (a x v) . (b x v)
    out_edge[(size_t)e * H + h] = efeat[(size_t)e * H + h] + g_gf[(size_t)e * H + h] * sum_phi;
}

// ---------------- node update ----------------
__global__ void node_final(float* __restrict__ out_scal,
                           float* __restrict__ out_vec) {
    int n = blockIdx.x;
    int h = threadIdx.x;
    float v1d[3], v2d[3];
    #pragma unroll
    for (int d = 0; d < 3; d++) {
        v1d[d] = g_wv[((size_t)n * 3 + d) * 256 + h];
        v2d[d] = g_wv[((size_t)n * 3 + d) * 256 + 128 + h];
    }
    float tri = v1d[0] * v2d[0] + v1d[1] * v2d[1] + v1d[2] * v2d[2];
    float sq  = v2d[0] * v2d[0] + v2d[1] * v2d[1] + v2d[2] * v2d[2];
    float nrm = sqrtf(sq + 1e-8f);
    float qua = nrm * nrm * nrm;
    float p1 = g_p[(size_t)n * 384 + h];
    float p2 = g_p[(size_t)n * 384 + 128 + h];
    float p3 = g_p[(size_t)n * 384 + 256 + h];
    out_scal[(size_t)n * H + h] = g_ns1[(size_t)n * H + h] + (qua + tri) * p1 + p2;
    #pragma unroll
    for (int d = 0; d < 3; d++) {
        out_vec[((size_t)n * 3 + d) * H + h] =
            g_nvec1[((size_t)n * 3 + d) * H + h] + v1d[d] * p3;
    }
}

// ---------------- launch ----------------
extern "C" void kernel_launch(void* const* d_in, const int* in_sizes, int n_in,
                              void* d_out, int out_size) {
    const float* node_scalar = (const float*)d_in[0];
    const float* node_vector = (const float*)d_in[1];
    const int*   edge_index  = (const int*)  d_in[2];
    const float* dist        = (const float*)d_in[3];
    const float* edge_feats  = (const float*)d_in[4];
    const float* edge_vector = (const float*)d_in[5];
    const float* ln_gamma    = (const float*)d_in[6];
    const float* ln_beta     = (const float*)d_in[7];
    const float* alpha       = (const float*)d_in[8];
    const float* W_cross     = (const float*)d_in[9];
    const float* W_node      = (const float*)d_in[10];
    const float* b_node      = (const float*)d_in[11];
    const float* W_edge      = (const float*)d_in[12];
    const float* b_edge      = (const float*)d_in[13];
    const float* W_p1        = (const float*)d_in[14];
    const float* b_p1        = (const float*)d_in[15];
    const float* W_p2        = (const float*)d_in[16];
    const float* b_p2        = (const float*)d_in[17];
    const float* W_vec       = (const float*)d_in[18];
    const float* W_f         = (const float*)d_in[19];
    const float* b_f         = (const float*)d_in[20];

    float* out = (float*)d_out;
    float* out_scal = out;                                  // [N,H]
    float* out_vec  = out + (size_t)N_NODES * H;            // [N,3,H]
    float* out_edge = out + (size_t)N_NODES * H * 4;        // [E,H]

    float* p_scalar_out; cudaGetSymbolAddress((void**)&p_scalar_out, g_scalar_out);
    float* p_ns;         cudaGetSymbolAddress((void**)&p_ns, g_ns);
    float* p_ef;         cudaGetSymbolAddress((void**)&p_ef, g_ef);
    float* p_msg;        cudaGetSymbolAddress((void**)&p_msg, g_msg);
    float* p_s;          cudaGetSymbolAddress((void**)&p_s, g_s);
    float* p_gf;         cudaGetSymbolAddress((void**)&p_gf, g_gf);
    float* p_nv;         cudaGetSymbolAddress((void**)&p_nv, g_nv);
    float* p_ns1;        cudaGetSymbolAddress((void**)&p_ns1, g_ns1);
    float* p_nvec1;      cudaGetSymbolAddress((void**)&p_nvec1, g_nvec1);
    float* p_wv;         cudaGetSymbolAddress((void**)&p_wv, g_wv);
    float* p_p;          cudaGetSymbolAddress((void**)&p_p, g_p);

    const int GB_N  = (N_NODES + 127) / 128;       // 157
    const int GB_E  = (N_EDGES + 127) / 128;       // 2500
    const int GB_3N = (3 * N_NODES + 127) / 128;   // 469

    // CSR build (independent of everything except edge_index)
    csr_zero<<<(N_NODES + 255) / 256, 256>>>();
    csr_hist<<<(N_EDGES + 255) / 256, 256>>>(edge_index);
    csr_scan<<<1, 1024>>>();
    csr_scatter<<<(N_EDGES + 255) / 256, 256>>>(edge_index);

    // scalar path
    ln_kernel<<<N_NODES, 128>>>(node_scalar, ln_gamma, ln_beta, p_scalar_out);
    gemm128<<<dim3(GB_N, 1), 256>>>(p_scalar_out, W_node, b_node, p_ns, N_NODES, 128, 0);
    gemm128<<<dim3(GB_E, 1), 256>>>(edge_feats, W_edge, b_edge, p_ef, N_EDGES, 128, 1);
    edge_msg<<<N_EDGES, 128>>>(edge_index, dist, alpha);
    gemm128<<<dim3(GB_E, 2), 256>>>(p_msg, W_p1, b_p1, p_s, N_EDGES, 256, 1);
    aggregate<<<N_NODES, 128>>>(edge_index, edge_vector, node_scalar, node_vector);

    // edge update (uses ORIGINAL node_vector)
    gemm128<<<dim3(GB_3N, 1), 256>>>(node_vector, W_cross, nullptr, p_nv, 3 * N_NODES, 128, 0);
    gemm128<<<dim3(GB_E, 1), 256>>>(edge_feats, W_f, b_f, p_gf, N_EDGES, 128, 1);
    edge_final<<<N_EDGES, 128>>>(edge_index, edge_vector, edge_feats, out_edge);

    // node update (uses aggregated ns1 / nvec1)
    gemm128<<<dim3(GB_3N, 2), 256>>>(p_nvec1, W_vec, nullptr, p_wv, 3 * N_NODES, 256, 0);
    gemm128<<<dim3(GB_N, 3), 256>>>(p_ns1, W_p2, b_p2, p_p, N_NODES, 384, 0);
    node_final<<<N_NODES, 128>>>(out_scal, out_vec);
}